// round 3
// baseline (speedup 1.0000x reference)
#include <cuda_runtime.h>
#include <cuda_bf16.h>
#include <mma.h>
#include <math.h>

using namespace nvcuda;

// ---------------------------------------------------------------------------
// Problem constants
// ---------------------------------------------------------------------------
#define PB     2
#define PT     2048
#define PC     2048
#define PH     32
#define PKVH   8
#define PHD    64
#define PKV    (PKVH * PHD)      // 512
#define PM     (PB * PT)         // 4096

// ---------------------------------------------------------------------------
// Device scratch (no cudaMalloc allowed)
// ---------------------------------------------------------------------------
__device__ float g_q[PM * PC];      // 32 MB
__device__ float g_k[PM * PKV];     //  8 MB
__device__ float g_v[PM * PKV];     //  8 MB
__device__ float g_attn[PM * PC];   // 32 MB

// ---------------------------------------------------------------------------
// TF32 tiled GEMM: C[M,N] = A[M,K] @ B[K,N], all row-major fp32.
// Block tile 128x128, K-step 32. 256 threads = 8 warps (4x2), warp tile 32x64.
// M % 128 == 0, N % 128 == 0, K % 32 == 0 (true for all our shapes).
// ---------------------------------------------------------------------------
#define GBM 128
#define GBN 128
#define GBK 32
#define GPAD 4

__global__ __launch_bounds__(256, 2)
void gemm_tf32(const float* __restrict__ A, const float* __restrict__ B,
               float* __restrict__ C, int M, int N, int K) {
    __shared__ float As[GBM][GBK + GPAD];   // 128 x 36
    __shared__ float Bs[GBK][GBN + GPAD];   // 32  x 132

    const int tid  = threadIdx.x;
    const int warp = tid >> 5;
    const int wm   = warp >> 1;       // 0..3 (M dir)
    const int wn   = warp & 1;        // 0..1 (N dir)
    const int bm   = blockIdx.y * GBM;
    const int bn   = blockIdx.x * GBN;

    wmma::fragment<wmma::accumulator, 16, 16, 8, float> acc[2][4];
    #pragma unroll
    for (int i = 0; i < 2; i++)
        #pragma unroll
        for (int j = 0; j < 4; j++)
            wmma::fill_fragment(acc[i][j], 0.0f);

    const int a_row = tid >> 3;            // 0..31
    const int a_col = (tid & 7) * 4;       // 0,4,...,28
    const int b_row = tid >> 5;            // 0..7
    const int b_col = (tid & 31) * 4;      // 0,4,...,124

    for (int k0 = 0; k0 < K; k0 += GBK) {
        #pragma unroll
        for (int p = 0; p < 4; p++) {
            int r = a_row + p * 32;
            *reinterpret_cast<float4*>(&As[r][a_col]) =
                *reinterpret_cast<const float4*>(&A[(size_t)(bm + r) * K + k0 + a_col]);
        }
        #pragma unroll
        for (int p = 0; p < 4; p++) {
            int r = b_row + p * 8;
            *reinterpret_cast<float4*>(&Bs[r][b_col]) =
                *reinterpret_cast<const float4*>(&B[(size_t)(k0 + r) * N + bn + b_col]);
        }
        __syncthreads();

        #pragma unroll
        for (int kk = 0; kk < GBK; kk += 8) {
            wmma::fragment<wmma::matrix_a, 16, 16, 8, wmma::precision::tf32, wmma::row_major> af[2];
            #pragma unroll
            for (int i = 0; i < 2; i++) {
                wmma::load_matrix_sync(af[i], &As[wm * 32 + i * 16][kk], GBK + GPAD);
                #pragma unroll
                for (int e = 0; e < af[i].num_elements; e++)
                    af[i].x[e] = wmma::__float_to_tf32(af[i].x[e]);
            }
            #pragma unroll
            for (int j = 0; j < 4; j++) {
                wmma::fragment<wmma::matrix_b, 16, 16, 8, wmma::precision::tf32, wmma::row_major> bf;
                wmma::load_matrix_sync(bf, &Bs[kk][wn * 64 + j * 16], GBN + GPAD);
                #pragma unroll
                for (int e = 0; e < bf.num_elements; e++)
                    bf.x[e] = wmma::__float_to_tf32(bf.x[e]);
                #pragma unroll
                for (int i = 0; i < 2; i++)
                    wmma::mma_sync(acc[i][j], af[i], bf, acc[i][j]);
            }
        }
        __syncthreads();
    }

    #pragma unroll
    for (int i = 0; i < 2; i++)
        #pragma unroll
        for (int j = 0; j < 4; j++)
            wmma::store_matrix_sync(
                &C[(size_t)(bm + wm * 32 + i * 16) * N + bn + wn * 64 + j * 16],
                acc[i][j], N, wmma::mem_row_major);
}

// ---------------------------------------------------------------------------
// RoPE, in place. buf: [rows, cols], cols is multiple of 64 (head_dim).
// Pair i (i=0..31) within each head: angle = t * 10000^(-i/32), t = row % T.
// Angle/sincos in double so accuracy vs the fp32 reference is sub-1e-5.
// ---------------------------------------------------------------------------
__global__ void rope_kernel(float* __restrict__ buf, int rows, int cols) {
    int idx = blockIdx.x * blockDim.x + threadIdx.x;
    int pairs = cols >> 1;
    if (idx >= rows * pairs) return;
    int row = idx / pairs;
    int p   = idx - row * pairs;
    int i    = p & 31;        // pair index within head
    int head = p >> 5;
    int t    = row & (PT - 1);

    double freq = exp(-(double)i * (9.210340371976184 / 32.0)); // ln(10000)/32
    double ang  = (double)t * freq;
    double s, c;
    sincos(ang, &s, &c);

    float* base = buf + (size_t)row * cols + head * 64 + 2 * i;
    float e = base[0], o = base[1];
    base[0] = e * (float)c - o * (float)s;
    base[1] = e * (float)s + o * (float)c;
}

// ---------------------------------------------------------------------------
// Flash attention (non-causal, GQA rep=4). One block = (b, h, 64-query tile).
// 128 threads = 4 warps. TF32 wmma for QK^T and PV, fp32 online softmax.
// Dynamic smem ~105 KB.
// ---------------------------------------------------------------------------
#define ALD 72   // 64 + 8 pad (288B rows, 16B-aligned)

__global__ __launch_bounds__(128)
void attn_kernel(const float* __restrict__ Q, const float* __restrict__ Kb,
                 const float* __restrict__ Vb, float* __restrict__ Out) {
    extern __shared__ float sm[];
    float* Qs   = sm;                  // 64*72
    float* Ks   = Qs  + 64 * ALD;      // 64*72
    float* Vs   = Ks  + 64 * ALD;      // 64*72
    float* Ss   = Vs  + 64 * ALD;      // 64*72
    float* Os   = Ss  + 64 * ALD;      // 64*64
    float* Ts   = Os  + 64 * 64;       // 64*64
    float* mrow = Ts  + 64 * 64;       // 64
    float* lrow = mrow + 64;           // 64
    float* crow = lrow + 64;           // 64

    const int tid  = threadIdx.x;
    const int warp = tid >> 5;
    const int qb = blockIdx.x, h = blockIdx.y, b = blockIdx.z;
    const int kh = h >> 2;                       // rep = 32/8 = 4
    const float scale = 0.125f;                  // 1/sqrt(64)

    const float* qg = Q  + ((size_t)(b * PT + qb * 64)) * PC + h * 64;
    const float* kg = Kb + ((size_t)b * PT) * PKV + kh * 64;
    const float* vg = Vb + ((size_t)b * PT) * PKV + kh * 64;

    // Load Q tile, zero O, init m/l.
    #pragma unroll
    for (int i = 0; i < 8; i++) {
        int idx = tid + i * 128;                 // 0..1023 float4s
        int r = idx >> 4, c = (idx & 15) * 4;
        *reinterpret_cast<float4*>(&Qs[r * ALD + c]) =
            *reinterpret_cast<const float4*>(&qg[(size_t)r * PC + c]);
    }
    #pragma unroll
    for (int i = 0; i < 8; i++)
        reinterpret_cast<float4*>(Os)[tid + i * 128] = make_float4(0.f, 0.f, 0.f, 0.f);
    if (tid < 64) { mrow[tid] = -1e30f; lrow[tid] = 0.f; }
    __syncthreads();

    for (int s0 = 0; s0 < PT; s0 += 64) {
        // Load K and V tiles
        #pragma unroll
        for (int i = 0; i < 8; i++) {
            int idx = tid + i * 128;
            int r = idx >> 4, c = (idx & 15) * 4;
            size_t g = (size_t)(s0 + r) * PKV + c;
            *reinterpret_cast<float4*>(&Ks[r * ALD + c]) =
                *reinterpret_cast<const float4*>(&kg[g]);
            *reinterpret_cast<float4*>(&Vs[r * ALD + c]) =
                *reinterpret_cast<const float4*>(&vg[g]);
        }
        __syncthreads();

        // S = Q @ K^T  (each warp: one 16-row strip x 64 cols)
        {
            wmma::fragment<wmma::accumulator, 16, 16, 8, float> sacc[4];
            #pragma unroll
            for (int j = 0; j < 4; j++) wmma::fill_fragment(sacc[j], 0.f);
            #pragma unroll
            for (int kk = 0; kk < 64; kk += 8) {
                wmma::fragment<wmma::matrix_a, 16, 16, 8, wmma::precision::tf32, wmma::row_major> af;
                wmma::load_matrix_sync(af, &Qs[warp * 16 * ALD + kk], ALD);
                #pragma unroll
                for (int e = 0; e < af.num_elements; e++)
                    af.x[e] = wmma::__float_to_tf32(af.x[e]);
                #pragma unroll
                for (int j = 0; j < 4; j++) {
                    wmma::fragment<wmma::matrix_b, 16, 16, 8, wmma::precision::tf32, wmma::col_major> bf;
                    wmma::load_matrix_sync(bf, &Ks[j * 16 * ALD + kk], ALD);
                    #pragma unroll
                    for (int e = 0; e < bf.num_elements; e++)
                        bf.x[e] = wmma::__float_to_tf32(bf.x[e]);
                    wmma::mma_sync(sacc[j], af, bf, sacc[j]);
                }
            }
            #pragma unroll
            for (int j = 0; j < 4; j++)
                wmma::store_matrix_sync(&Ss[warp * 16 * ALD + j * 16], sacc[j],
                                        ALD, wmma::mem_row_major);
        }
        __syncthreads();

        // Online softmax (one thread per row)
        if (tid < 64) {
            float* srow = &Ss[tid * ALD];
            float m_old = mrow[tid];
            float rm = m_old;
            #pragma unroll
            for (int c = 0; c < 64; c++) rm = fmaxf(rm, srow[c] * scale);
            float corr = __expf(m_old - rm);
            float sum = 0.f;
            #pragma unroll
            for (int c = 0; c < 64; c++) {
                float p = __expf(srow[c] * scale - rm);
                srow[c] = p;
                sum += p;
            }
            mrow[tid] = rm;
            lrow[tid] = lrow[tid] * corr + sum;
            crow[tid] = corr;
        }
        __syncthreads();

        // T = P @ V
        {
            wmma::fragment<wmma::accumulator, 16, 16, 8, float> oacc[4];
            #pragma unroll
            for (int j = 0; j < 4; j++) wmma::fill_fragment(oacc[j], 0.f);
            #pragma unroll
            for (int kk = 0; kk < 64; kk += 8) {
                wmma::fragment<wmma::matrix_a, 16, 16, 8, wmma::precision::tf32, wmma::row_major> af;
                wmma::load_matrix_sync(af, &Ss[warp * 16 * ALD + kk], ALD);
                #pragma unroll
                for (int e = 0; e < af.num_elements; e++)
                    af.x[e] = wmma::__float_to_tf32(af.x[e]);
                #pragma unroll
                for (int j = 0; j < 4; j++) {
                    wmma::fragment<wmma::matrix_b, 16, 16, 8, wmma::precision::tf32, wmma::row_major> bf;
                    wmma::load_matrix_sync(bf, &Vs[kk * ALD + j * 16], ALD);
                    #pragma unroll
                    for (int e = 0; e < bf.num_elements; e++)
                        bf.x[e] = wmma::__float_to_tf32(bf.x[e]);
                    wmma::mma_sync(oacc[j], af, bf, oacc[j]);
                }
            }
            #pragma unroll
            for (int j = 0; j < 4; j++)
                wmma::store_matrix_sync(&Ts[warp * 16 * 64 + j * 16], oacc[j],
                                        64, wmma::mem_row_major);
        }
        __syncthreads();

        // O = O * corr + T
        #pragma unroll
        for (int i = 0; i < 32; i++) {
            int idx = tid + i * 128;            // 0..4095
            int r = idx >> 6;
            Os[idx] = Os[idx] * crow[r] + Ts[idx];
        }
        __syncthreads();
    }

    // Write O / l
    float* og = Out + ((size_t)(b * PT + qb * 64)) * PC + h * 64;
    #pragma unroll
    for (int i = 0; i < 32; i++) {
        int idx = tid + i * 128;
        int r = idx >> 6, c = idx & 63;
        og[(size_t)r * PC + c] = Os[idx] / lrow[r];
    }
}

#define ATTN_SMEM_BYTES ((4 * 64 * ALD + 2 * 64 * 64 + 3 * 64) * sizeof(float))

// ---------------------------------------------------------------------------
// Launch
// ---------------------------------------------------------------------------
extern "C" void kernel_launch(void* const* d_in, const int* in_sizes, int n_in,
                              void* d_out, int out_size) {
    const float* x  = (const float*)d_in[0];
    const float* wq = (const float*)d_in[1];
    const float* wk = (const float*)d_in[2];
    const float* wv = (const float*)d_in[3];
    const float* wo = (const float*)d_in[4];
    float* out = (float*)d_out;

    float *q, *k, *v, *a;
    cudaGetSymbolAddress((void**)&q, g_q);
    cudaGetSymbolAddress((void**)&k, g_k);
    cudaGetSymbolAddress((void**)&v, g_v);
    cudaGetSymbolAddress((void**)&a, g_attn);

    // QKV projections
    gemm_tf32<<<dim3(PC / GBN,  PM / GBM), 256>>>(x, wq, q, PM, PC,  PC);
    gemm_tf32<<<dim3(PKV / GBN, PM / GBM), 256>>>(x, wk, k, PM, PKV, PC);
    gemm_tf32<<<dim3(PKV / GBN, PM / GBM), 256>>>(x, wv, v, PM, PKV, PC);

    // RoPE on q and k
    {
        int qpairs = PM * (PC / 2);
        rope_kernel<<<(qpairs + 255) / 256, 256>>>(q, PM, PC);
        int kpairs = PM * (PKV / 2);
        rope_kernel<<<(kpairs + 255) / 256, 256>>>(k, PM, PKV);
    }

    // Attention
    cudaFuncSetAttribute(attn_kernel, cudaFuncAttributeMaxDynamicSharedMemorySize,
                         (int)ATTN_SMEM_BYTES);
    attn_kernel<<<dim3(PT / 64, PH, PB), 128, ATTN_SMEM_BYTES>>>(q, k, v, a);

    // Output projection
    gemm_tf32<<<dim3(PC / GBN, PM / GBM), 256>>>(a, wo, out, PM, PC, PC);
}

// round 6
// speedup vs baseline: 1.2120x; 1.2120x over previous
#include <cuda_runtime.h>
#include <cuda_bf16.h>
#include <mma.h>
#include <math.h>

using namespace nvcuda;

// ---------------------------------------------------------------------------
// Problem constants
// ---------------------------------------------------------------------------
#define PB     2
#define PT     2048
#define PC     2048
#define PH     32
#define PKVH   8
#define PHD    64
#define PKV    (PKVH * PHD)      // 512
#define PM     (PB * PT)         // 4096

// ---------------------------------------------------------------------------
// Device scratch (no cudaMalloc allowed)
// ---------------------------------------------------------------------------
__device__ float g_q[PM * PC];      // 32 MB
__device__ float g_k[PM * PKV];     //  8 MB
__device__ float g_v[PM * PKV];     //  8 MB
__device__ float g_attn[PM * PC];   // 32 MB
__device__ float g_cos[PT * 32];
__device__ float g_sin[PT * 32];

// ---------------------------------------------------------------------------
// cp.async helpers
// ---------------------------------------------------------------------------
__device__ __forceinline__ void cp_async16(void* s, const void* g) {
    unsigned sa = (unsigned)__cvta_generic_to_shared(s);
    asm volatile("cp.async.cg.shared.global [%0], [%1], 16;" :: "r"(sa), "l"(g));
}
__device__ __forceinline__ void cp_commit() {
    asm volatile("cp.async.commit_group;");
}
template<int N> __device__ __forceinline__ void cp_wait() {
    asm volatile("cp.async.wait_group %0;" :: "n"(N));
}

// ---------------------------------------------------------------------------
// TF32 GEMM: C[M,N] = A[M,K] @ B[K,N], row-major fp32, 2-stage cp.async
// pipeline. BM=128 fixed, BK=32. 256 threads = 8 warps.
//   <BN=256, WN=4>: warp tile 64x64 (wq / wo)
//   <BN=128, WN=2>: warp tile 32x64 (wk / wv)
// ---------------------------------------------------------------------------
template<int BN, int WN>
__global__ __launch_bounds__(256, 1)
void gemm_kernel(const float* __restrict__ A, const float* __restrict__ B,
                 float* __restrict__ C, int M, int N, int K) {
    constexpr int BM  = 128, BK = 32;
    constexpr int WMW = 8 / WN;          // warps in M
    constexpr int WTM = BM / WMW;        // warp tile M
    constexpr int WTN = BN / WN;         // warp tile N
    constexpr int FM  = WTM / 16, FN = WTN / 16;
    constexpr int AP  = BK + 4;          // A smem pitch (floats)
    constexpr int BP  = BN + 4;          // B smem pitch
    constexpr int ACH = BM * BK / 4 / 256;       // A float4 chunks / thread
    constexpr int BCH = BK * (BN / 4) / 256;     // B float4 chunks / thread

    extern __shared__ float smem[];
    float* As = smem;                    // 2 * BM * AP
    float* Bs = smem + 2 * BM * AP;      // 2 * BK * BP

    const int tid  = threadIdx.x;
    const int warp = tid >> 5;
    const int wm   = warp / WN;
    const int wn   = warp % WN;
    const int bm   = blockIdx.y * BM;
    const int bn   = blockIdx.x * BN;

    wmma::fragment<wmma::accumulator, 16, 16, 8, float> acc[FM][FN];
    #pragma unroll
    for (int i = 0; i < FM; i++)
        #pragma unroll
        for (int j = 0; j < FN; j++)
            wmma::fill_fragment(acc[i][j], 0.0f);

    auto load_stage = [&](int s, int k0) {
        #pragma unroll
        for (int i = 0; i < ACH; i++) {
            int idx = tid + i * 256;
            int r = idx >> 3, c = (idx & 7) * 4;
            cp_async16(&As[(s * BM + r) * AP + c],
                       &A[(size_t)(bm + r) * K + k0 + c]);
        }
        #pragma unroll
        for (int i = 0; i < BCH; i++) {
            int idx = tid + i * 256;
            int r = idx / (BN / 4), c = (idx % (BN / 4)) * 4;
            cp_async16(&Bs[(s * BK + r) * BP + c],
                       &B[(size_t)(k0 + r) * N + bn + c]);
        }
    };

    const int KT = K / BK;
    load_stage(0, 0);
    cp_commit();

    for (int kt = 0; kt < KT; kt++) {
        if (kt + 1 < KT) {
            load_stage((kt + 1) & 1, (kt + 1) * BK);
            cp_commit();
            cp_wait<1>();
        } else {
            cp_wait<0>();
        }
        __syncthreads();

        const float* as = &As[(kt & 1) * BM * AP];
        const float* bs = &Bs[(kt & 1) * BK * BP];

        #pragma unroll
        for (int kk = 0; kk < BK; kk += 8) {
            wmma::fragment<wmma::matrix_a, 16, 16, 8, wmma::precision::tf32, wmma::row_major> af[FM];
            #pragma unroll
            for (int i = 0; i < FM; i++) {
                wmma::load_matrix_sync(af[i], &as[(wm * WTM + i * 16) * AP + kk], AP);
                #pragma unroll
                for (int e = 0; e < af[i].num_elements; e++)
                    af[i].x[e] = wmma::__float_to_tf32(af[i].x[e]);
            }
            #pragma unroll
            for (int j = 0; j < FN; j++) {
                wmma::fragment<wmma::matrix_b, 16, 16, 8, wmma::precision::tf32, wmma::row_major> bf;
                wmma::load_matrix_sync(bf, &bs[kk * BP + wn * WTN + j * 16], BP);
                #pragma unroll
                for (int e = 0; e < bf.num_elements; e++)
                    bf.x[e] = wmma::__float_to_tf32(bf.x[e]);
                #pragma unroll
                for (int i = 0; i < FM; i++)
                    wmma::mma_sync(acc[i][j], af[i], bf, acc[i][j]);
            }
        }
        __syncthreads();
    }

    #pragma unroll
    for (int i = 0; i < FM; i++)
        #pragma unroll
        for (int j = 0; j < FN; j++)
            wmma::store_matrix_sync(
                &C[(size_t)(bm + wm * WTM + i * 16) * N + bn + wn * WTN + j * 16],
                acc[i][j], N, wmma::mem_row_major);
}

#define GEMM_BIG_SMEM  ((2 * 128 * 36 + 2 * 32 * 260) * sizeof(float))   // 103424
#define GEMM_KV_SMEM   ((2 * 128 * 36 + 2 * 32 * 132) * sizeof(float))   //  70656

// ---------------------------------------------------------------------------
// RoPE tables (double precision, computed once per launch — cheap)
// ---------------------------------------------------------------------------
__global__ void rope_table_kernel() {
    int idx = blockIdx.x * blockDim.x + threadIdx.x;
    if (idx >= PT * 32) return;
    int t = idx >> 5, i = idx & 31;
    double freq = exp(-(double)i * (9.210340371976184 / 32.0)); // ln(10000)/32
    double s, c;
    sincos((double)t * freq, &s, &c);
    g_cos[idx] = (float)c;
    g_sin[idx] = (float)s;
}

// RoPE apply, in place, memory-bound fp32. buf: [rows, cols].
__global__ void rope_apply_kernel(float* __restrict__ buf, int rows, int cols) {
    int idx = blockIdx.x * blockDim.x + threadIdx.x;
    int pairs = cols >> 1;
    if (idx >= rows * pairs) return;
    int row = idx / pairs;
    int p   = idx - row * pairs;
    int i   = p & 31;                  // pair index within head (hd/2 = 32)
    int t   = row & (PT - 1);
    float c = g_cos[t * 32 + i];
    float s = g_sin[t * 32 + i];
    float2 v = reinterpret_cast<float2*>(buf)[idx];
    float2 r;
    r.x = v.x * c - v.y * s;
    r.y = v.x * s + v.y * c;
    reinterpret_cast<float2*>(buf)[idx] = r;
}

// ---------------------------------------------------------------------------
// Flash attention (non-causal, GQA rep=4).
// One block = (b, h, 128-query tile). 256 threads = 8 warps, warp w owns
// rows [w*16, w*16+16). KV tiles of 64, cp.async double-buffered.
// smem regions (floats):
//   Qs 128*72 | Ks 2*64*72 | Vs 2*64*72 | Ss 128*72 | Ts 128*64 | Os 128*64
//   | mrow 128 | lrow 128 | crow 128      => 53,632 floats = 214,528 bytes
// ---------------------------------------------------------------------------
#define ALD 72   // 64 + 8 pad

__global__ __launch_bounds__(256, 1)
void attn_kernel(const float* __restrict__ Q, const float* __restrict__ Kb,
                 const float* __restrict__ Vb, float* __restrict__ Out) {
    extern __shared__ float sm[];
    float* Qs   = sm;                   // 128*72
    float* Ks   = Qs  + 128 * ALD;      // 2 stages * 64*72
    float* Vs   = Ks  + 2 * 64 * ALD;   // 2 stages * 64*72
    float* Ss   = Vs  + 2 * 64 * ALD;   // 128*72
    float* Ts   = Ss  + 128 * ALD;      // 128*64
    float* Os   = Ts  + 128 * 64;       // 128*64
    float* mrow = Os  + 128 * 64;       // 128
    float* lrow = mrow + 128;           // 128
    float* crow = lrow + 128;           // 128

    const int tid  = threadIdx.x;
    const int warp = tid >> 5;
    const int qb = blockIdx.x, h = blockIdx.y, b = blockIdx.z;
    const int kh = h >> 2;                        // rep = 4
    const float scale = 0.125f;                   // 1/sqrt(64)

    const float* qg = Q  + ((size_t)(b * PT + qb * 128)) * PC + h * 64;
    const float* kg = Kb + ((size_t)b * PT) * PKV + kh * 64;
    const float* vg = Vb + ((size_t)b * PT) * PKV + kh * 64;

    // Load Q tile (128x64), zero O, init m/l.
    #pragma unroll
    for (int i = 0; i < 8; i++) {
        int idx = tid + i * 256;                  // 2048 float4 chunks
        int r = idx >> 4, c = (idx & 15) * 4;
        cp_async16(&Qs[r * ALD + c], &qg[(size_t)r * PC + c]);
    }
    #pragma unroll
    for (int i = 0; i < 8; i++)
        reinterpret_cast<float4*>(Os)[tid + i * 256] = make_float4(0.f, 0.f, 0.f, 0.f);
    if (tid < 128) { mrow[tid] = -1e30f; lrow[tid] = 0.f; }

    auto load_kv = [&](int s, int s0) {
        #pragma unroll
        for (int i = 0; i < 4; i++) {             // 1024 chunks per tensor
            int idx = tid + i * 256;
            int r = idx >> 4, c = (idx & 15) * 4;
            size_t g = (size_t)(s0 + r) * PKV + c;
            cp_async16(&Ks[(s * 64 + r) * ALD + c], &kg[g]);
            cp_async16(&Vs[(s * 64 + r) * ALD + c], &vg[g]);
        }
    };

    load_kv(0, 0);              // same commit group as Q
    cp_commit();

    const int NT = PT / 64;     // 32 KV tiles
    for (int it = 0; it < NT; it++) {
        if (it + 1 < NT) {
            load_kv((it + 1) & 1, (it + 1) * 64);
            cp_commit();
            cp_wait<1>();
        } else {
            cp_wait<0>();
        }
        __syncthreads();

        const float* ks = &Ks[(it & 1) * 64 * ALD];
        const float* vs = &Vs[(it & 1) * 64 * ALD];

        // S = Q @ K^T  (warp: 16 rows x 64 keys)
        {
            wmma::fragment<wmma::accumulator, 16, 16, 8, float> sacc[4];
            #pragma unroll
            for (int j = 0; j < 4; j++) wmma::fill_fragment(sacc[j], 0.f);
            #pragma unroll
            for (int kk = 0; kk < 64; kk += 8) {
                wmma::fragment<wmma::matrix_a, 16, 16, 8, wmma::precision::tf32, wmma::row_major> af;
                wmma::load_matrix_sync(af, &Qs[warp * 16 * ALD + kk], ALD);
                #pragma unroll
                for (int e = 0; e < af.num_elements; e++)
                    af.x[e] = wmma::__float_to_tf32(af.x[e]);
                #pragma unroll
                for (int j = 0; j < 4; j++) {
                    wmma::fragment<wmma::matrix_b, 16, 16, 8, wmma::precision::tf32, wmma::col_major> bf;
                    wmma::load_matrix_sync(bf, &ks[j * 16 * ALD + kk], ALD);
                    #pragma unroll
                    for (int e = 0; e < bf.num_elements; e++)
                        bf.x[e] = wmma::__float_to_tf32(bf.x[e]);
                    wmma::mma_sync(sacc[j], af, bf, sacc[j]);
                }
            }
            #pragma unroll
            for (int j = 0; j < 4; j++)
                wmma::store_matrix_sync(&Ss[warp * 16 * ALD + j * 16], sacc[j],
                                        ALD, wmma::mem_row_major);
        }
        __syncthreads();

        // Online softmax: 2 threads per row (tid and tid^1), 32 cols each.
        {
            int row  = tid >> 1;
            int half = tid & 1;
            float* srow = &Ss[row * ALD + half * 32];
            float m_old = mrow[row];
            float rm = -1e30f;
            #pragma unroll
            for (int c = 0; c < 32; c++) rm = fmaxf(rm, srow[c] * scale);
            rm = fmaxf(rm, __shfl_xor_sync(0xFFFFFFFFu, rm, 1));
            rm = fmaxf(rm, m_old);
            float sum = 0.f;
            #pragma unroll
            for (int c = 0; c < 32; c++) {
                float p = __expf(srow[c] * scale - rm);
                srow[c] = p;
                sum += p;
            }
            sum += __shfl_xor_sync(0xFFFFFFFFu, sum, 1);
            if (half == 0) {
                float corr = __expf(m_old - rm);
                mrow[row] = rm;
                lrow[row] = lrow[row] * corr + sum;
                crow[row] = corr;
            }
        }
        __syncthreads();

        // T = P @ V  (warp: 16 rows x 64 dims)
        {
            wmma::fragment<wmma::accumulator, 16, 16, 8, float> oacc[4];
            #pragma unroll
            for (int j = 0; j < 4; j++) wmma::fill_fragment(oacc[j], 0.f);
            #pragma unroll
            for (int kk = 0; kk < 64; kk += 8) {
                wmma::fragment<wmma::matrix_a, 16, 16, 8, wmma::precision::tf32, wmma::row_major> af;
                wmma::load_matrix_sync(af, &Ss[warp * 16 * ALD + kk], ALD);
                #pragma unroll
                for (int e = 0; e < af.num_elements; e++)
                    af.x[e] = wmma::__float_to_tf32(af.x[e]);
                #pragma unroll
                for (int j = 0; j < 4; j++) {
                    wmma::fragment<wmma::matrix_b, 16, 16, 8, wmma::precision::tf32, wmma::row_major> bf;
                    wmma::load_matrix_sync(bf, &vs[kk * ALD + j * 16], ALD);
                    #pragma unroll
                    for (int e = 0; e < bf.num_elements; e++)
                        bf.x[e] = wmma::__float_to_tf32(bf.x[e]);
                    wmma::mma_sync(oacc[j], af, bf, oacc[j]);
                }
            }
            #pragma unroll
            for (int j = 0; j < 4; j++)
                wmma::store_matrix_sync(&Ts[warp * 16 * 64 + j * 16], oacc[j],
                                        64, wmma::mem_row_major);
        }
        __syncthreads();

        // O = O * corr + T
        #pragma unroll
        for (int i = 0; i < 32; i++) {
            int idx = tid + i * 256;              // 0..8191
            int r = idx >> 6;
            Os[idx] = Os[idx] * crow[r] + Ts[idx];
        }
        __syncthreads();
    }

    // Write O / l
    float* og = Out + ((size_t)(b * PT + qb * 128)) * PC + h * 64;
    #pragma unroll
    for (int i = 0; i < 32; i++) {
        int idx = tid + i * 256;
        int r = idx >> 6, c = idx & 63;
        og[(size_t)r * PC + c] = Os[idx] / lrow[r];
    }
}

// FIXED: count BOTH 128*ALD regions (Qs and Ss). 53,632 floats = 214,528 B.
#define ATTN_SMEM_BYTES ((2 * 128 * ALD + 4 * 64 * ALD + 2 * 128 * 64 + 3 * 128) * sizeof(float))

// ---------------------------------------------------------------------------
// Launch
// ---------------------------------------------------------------------------
extern "C" void kernel_launch(void* const* d_in, const int* in_sizes, int n_in,
                              void* d_out, int out_size) {
    const float* x  = (const float*)d_in[0];
    const float* wq = (const float*)d_in[1];
    const float* wk = (const float*)d_in[2];
    const float* wv = (const float*)d_in[3];
    const float* wo = (const float*)d_in[4];
    float* out = (float*)d_out;

    float *q, *k, *v, *a;
    cudaGetSymbolAddress((void**)&q, g_q);
    cudaGetSymbolAddress((void**)&k, g_k);
    cudaGetSymbolAddress((void**)&v, g_v);
    cudaGetSymbolAddress((void**)&a, g_attn);

    cudaFuncSetAttribute(gemm_kernel<256, 4>,
                         cudaFuncAttributeMaxDynamicSharedMemorySize, (int)GEMM_BIG_SMEM);
    cudaFuncSetAttribute(gemm_kernel<128, 2>,
                         cudaFuncAttributeMaxDynamicSharedMemorySize, (int)GEMM_KV_SMEM);
    cudaFuncSetAttribute(attn_kernel,
                         cudaFuncAttributeMaxDynamicSharedMemorySize, (int)ATTN_SMEM_BYTES);

    // RoPE tables (deterministic, recomputed every launch; ~5us)
    rope_table_kernel<<<(PT * 32 + 255) / 256, 256>>>();

    // QKV projections
    gemm_kernel<256, 4><<<dim3(PC / 256,  PM / 128), 256, GEMM_BIG_SMEM>>>(x, wq, q, PM, PC,  PC);
    gemm_kernel<128, 2><<<dim3(PKV / 128, PM / 128), 256, GEMM_KV_SMEM>>>(x, wk, k, PM, PKV, PC);
    gemm_kernel<128, 2><<<dim3(PKV / 128, PM / 128), 256, GEMM_KV_SMEM>>>(x, wv, v, PM, PKV, PC);

    // RoPE on q and k (fp32, table-driven, memory-bound)
    {
        int qpairs = PM * (PC / 2);
        rope_apply_kernel<<<(qpairs + 255) / 256, 256>>>(q, PM, PC);
        int kpairs = PM * (PKV / 2);
        rope_apply_kernel<<<(kpairs + 255) / 256, 256>>>(k, PM, PKV);
    }

    // Attention
    attn_kernel<<<dim3(PT / 128, PH, PB), 256, ATTN_SMEM_BYTES>>>(q, k, v, a);

    // Output projection
    gemm_kernel<256, 4><<<dim3(PC / 256, PM / 128), 256, GEMM_BIG_SMEM>>>(a, wo, out, PM, PC, PC);
}